// round 13
// baseline (speedup 1.0000x reference)
#include <cuda_runtime.h>

// LSTM B=8192, T=512, I=12, H=20 (i,f,g,o), zero init; Linear(H->10) on h_T.
//
// R13 = R11 base + critical-section surgery:
//  - x-part of step t+1 computed BEFORE the end-of-step barrier into the dead
//    accumulator regs (independent of h(t+1)); each step's in-barrier work is
//    only the h-part GEMV + epilogue. At chunk boundaries the x-part runs
//    right after the staging sync.
//  - Group phase stagger: barrier domain phase = 2*(blockIdx&1)+gid does
//    phase*3 extra group bars before the loop (~140 cyc apart) to decorrelate
//    GEMV vs epilogue phases across the 4 domains per SM.
//  - Thread = 2 gate rows x 1 unit x 4 batches, 32 u64 weights in regs;
//    partner (lane^1) holds the other 2 gates, combined via shfl.xor(1).
//  - Block 320 thr = 2 independent 160-thr groups (named barriers), BPB=32,
//    grid=256, __launch_bounds__(320,2), TCH=4.

#define LSTM_H   20
#define LSTM_I   12
#define LSTM_T   512
#define BPB      32
#define THREADS  320
#define GRID     256
#define XROW     52    // floats per batch row in xs (208B, 16B-aligned)

typedef unsigned long long u64;
typedef unsigned int       u32;

__device__ __forceinline__ u64 pack2(float lo, float hi) {
    u64 r; asm("mov.b64 %0, {%1, %2};" : "=l"(r) : "f"(lo), "f"(hi)); return r;
}
__device__ __forceinline__ void unpack2(u64 v, float& lo, float& hi) {
    asm("mov.b64 {%0, %1}, %2;" : "=f"(lo), "=f"(hi) : "l"(v));
}
__device__ __forceinline__ u64 fma2(u64 a, u64 b, u64 c) {
    u64 r; asm("fma.rn.f32x2 %0, %1, %2, %3;" : "=l"(r) : "l"(a), "l"(b), "l"(c));
    return r;
}
__device__ __forceinline__ float hadd2(u64 v) {
    float lo, hi; unpack2(v, lo, hi); return lo + hi;
}
__device__ __forceinline__ float tanhA(float x) {
    float y; asm("tanh.approx.f32 %0, %1;" : "=f"(y) : "f"(x)); return y;
}
__device__ __forceinline__ float sigA(float x) {
    return fmaf(tanhA(0.5f * x), 0.5f, 0.5f);
}
__device__ __forceinline__ void cp_async16(u32 smem_dst, const void* gsrc) {
    asm volatile("cp.async.ca.shared.global [%0], [%1], 16;\n"
                 :: "r"(smem_dst), "l"(gsrc) : "memory");
}
__device__ __forceinline__ void cp_commit() {
    asm volatile("cp.async.commit_group;\n" ::: "memory");
}
template<int N>
__device__ __forceinline__ void cp_wait() {
    asm volatile("cp.async.wait_group %0;\n" :: "n"(N) : "memory");
}
__device__ __forceinline__ void group_bar(int id) {
    asm volatile("bar.sync %0, %1;" :: "r"(id), "r"(160) : "memory");
}

// x-part: re-init accs from bias and accumulate 6 u64 of x.
__device__ __forceinline__ void gemvX(const u64* __restrict__ xr,
                                      const u64* w0, const u64* w1,
                                      u64 binit0, u64 binit1,
                                      u64& a0, u64& a1)
{
    a0 = binit0; a1 = binit1;
    #pragma unroll
    for (int k = 0; k < 6; k += 2) {
        ulonglong2 xv = *(const ulonglong2*)(xr + k);
        a0 = fma2(w0[k], xv.x, a0); a0 = fma2(w0[k+1], xv.y, a0);
        a1 = fma2(w1[k], xv.x, a1); a1 = fma2(w1[k+1], xv.y, a1);
    }
}
// h-part: accumulate 10 u64 of h onto existing accs.
__device__ __forceinline__ void gemvH(const u64* __restrict__ hr,
                                      const u64* w0, const u64* w1,
                                      u64& a0, u64& a1)
{
    #pragma unroll
    for (int k = 0; k < 10; k += 2) {
        ulonglong2 hv = *(const ulonglong2*)(hr + k);
        a0 = fma2(w0[6+k], hv.x, a0); a0 = fma2(w0[6+k+1], hv.y, a0);
        a1 = fma2(w1[6+k], hv.x, a1); a1 = fma2(w1[6+k+1], hv.y, a1);
    }
}

__global__ void __launch_bounds__(THREADS, 2)
lstm_kernel(const float* __restrict__ x,
            const float* __restrict__ w_ih,
            const float* __restrict__ w_hh,
            const float* __restrict__ b_ih,
            const float* __restrict__ b_hh,
            const float* __restrict__ w_out,
            const float* __restrict__ b_out,
            float* __restrict__ out)
{
    __shared__ __align__(16) float wcomb[80 * 32];           // 10240 B
    __shared__ __align__(16) float hbuf[2][BPB * LSTM_H];    //  5120 B
    __shared__ __align__(16) float xs[2][BPB * XROW];        // 13312 B

    const int tid  = threadIdx.x;
    const int gid  = tid / 160;          // group 0/1 (owns 16 batches)
    const int ltid = tid - gid * 160;
    const int quad = tid / 40;           // 0..7 (global)
    const int r    = tid % 40;
    const int u    = r >> 1;             // unit 0..19
    const int gh   = r & 1;              // 0 -> (i,g), 1 -> (f,o)
    const int b0   = blockIdx.x * BPB;
    const int q4   = quad * 4;
    const int barid = 1 + gid;

    const int row0 = gh ? (20 + u) : u;          // f : i
    const int row1 = gh ? (60 + u) : (40 + u);   // o : g

    // ---- stage combined weight rows into SMEM ----
    for (int i = tid; i < 80 * LSTM_I; i += THREADS) {
        int rr = i / LSTM_I, k = i - rr * LSTM_I;
        wcomb[rr * 32 + k] = w_ih[i];
    }
    for (int i = tid; i < 80 * LSTM_H; i += THREADS) {
        int rr = i / LSTM_H, k = i - rr * LSTM_H;
        wcomb[rr * 32 + 12 + k] = w_hh[i];
    }
    for (int i = tid; i < BPB * LSTM_H; i += THREADS) hbuf[0][i] = 0.f;

    const u64 binit0 = pack2(b_ih[row0] + b_hh[row0], 0.f);
    const u64 binit1 = pack2(b_ih[row1] + b_hh[row1], 0.f);

    // ---- cp.async: group loads its own 16 batches, chunk0/1 ----
    const float4* x4 = (const float4*)x;
    const u32 xs_base = (u32)__cvta_generic_to_shared(&xs[0][0]);
    {
        #pragma unroll 1
        for (int e = ltid; e < 16 * 12; e += 160) {
            int b = gid * 16 + e / 12, q = e - (e / 12) * 12;
            cp_async16(xs_base + (u32)((b * XROW + q * 4) * 4),
                       x4 + (long)(b0 + b) * 1536 + q);
        }
        cp_commit();
        #pragma unroll 1
        for (int e = ltid; e < 16 * 12; e += 160) {
            int b = gid * 16 + e / 12, q = e - (e / 12) * 12;
            cp_async16(xs_base + (u32)((BPB * XROW + b * XROW + q * 4) * 4),
                       x4 + (long)(b0 + b) * 1536 + 12 + q);
        }
        cp_commit();
    }
    cp_wait<1>();
    __syncthreads();       // wcomb + hbuf + chunk0 visible

    // ---- this thread's 2 gate rows into registers (32 u64 = 64 regs) ----
    u64 w0[16], w1[16];
    {
        const u64* p0 = (const u64*)&wcomb[row0 * 32];
        const u64* p1 = (const u64*)&wcomb[row1 * 32];
        #pragma unroll
        for (int k = 0; k < 16; k++) { w0[k] = p0[k]; w1[k] = p1[k]; }
    }

    // ---- phase stagger: decorrelate the 4 barrier domains per SM ----
    {
        const int phase = ((blockIdx.x & 1) << 1) | gid;   // 0..3
        for (int s = 0; s < phase * 3; s++) group_bar(barid);
    }

    float c0 = 0.f, c1 = 0.f;   // my 2 owned batches: q4+2*gh, q4+2*gh+1

    // accs pre-loaded with bias + x-part of step 0
    u64 a0[4], a1[4];
    #pragma unroll
    for (int j = 0; j < 4; j++)
        gemvX((const u64*)&xs[0][(q4 + j) * XROW], w0, w1, binit0, binit1,
              a0[j], a1[j]);

    #pragma unroll 1
    for (int t = 0; t < LSTM_T; t++) {
        const int tt = t & 3;
        if (tt == 0 && t > 0) {
            cp_wait<0>();          // this chunk landed
            group_bar(barid);      // group done reading old buffer
            if (t + 4 < LSTM_T) {
                const int nbuf = ((t >> 2) + 1) & 1;
                #pragma unroll 1
                for (int e = ltid; e < 16 * 12; e += 160) {
                    int b = gid * 16 + e / 12, q = e - (e / 12) * 12;
                    cp_async16(xs_base + (u32)((nbuf * BPB * XROW + b * XROW + q * 4) * 4),
                               x4 + (long)(b0 + b) * 1536 + (long)(t + 4) * 3 + q);
                }
                cp_commit();
            }
            // x-part for this step (tt == 0) from the fresh buffer
            const int buf = (t >> 2) & 1;
            #pragma unroll
            for (int j = 0; j < 4; j++)
                gemvX((const u64*)&xs[buf][(q4 + j) * XROW], w0, w1,
                      binit0, binit1, a0[j], a1[j]);
        }

        const int buf = (t >> 2) & 1;
        const int cur = t & 1, nxt = cur ^ 1;

        // ---- h-part GEMV (critical section) ----
        const float* hb = &hbuf[cur][0];
        #pragma unroll
        for (int j = 0; j < 4; j++)
            gemvH((const u64*)(hb + (q4 + j) * LSTM_H), w0, w1, a0[j], a1[j]);

        float gA[4], gB[4];
        #pragma unroll
        for (int j = 0; j < 4; j++) { gA[j] = hadd2(a0[j]); gB[j] = hadd2(a1[j]); }

        // ---- epilogue, pairs p=0 (j 0/2) and p=1 (j 1/3) ----
        float* hn = &hbuf[nxt][0];
        #pragma unroll
        for (int p = 0; p < 2; p++) {
            float sendA = gh ? gA[p]     : gA[2 + p];
            float sendB = gh ? gB[p]     : gB[2 + p];
            float ownA  = gh ? gA[2 + p] : gA[p];
            float ownB  = gh ? gB[2 + p] : gB[p];
            float recvA = __shfl_xor_sync(0xffffffffu, sendA, 1);
            float recvB = __shfl_xor_sync(0xffffffffu, sendB, 1);
            float gi = gh ? recvA : ownA;
            float gg = gh ? recvB : ownB;
            float gf = gh ? ownA  : recvA;
            float go = gh ? ownB  : recvB;
            float c  = p ? c1 : c0;
            c = sigA(gf) * c + sigA(gi) * tanhA(gg);
            if (p) c1 = c; else c0 = c;
            hn[(q4 + 2 * gh + p) * LSTM_H + u] = sigA(go) * tanhA(c);
        }

        // ---- x-part for step t+1 (same chunk only): fills the shadow ----
        if (((t + 1) & 3) != 0) {
            const int ttn = (t + 1) & 3;
            #pragma unroll
            for (int j = 0; j < 4; j++)
                gemvX((const u64*)&xs[buf][(q4 + j) * XROW + ttn * 12], w0, w1,
                      binit0, binit1, a0[j], a1[j]);
        }

        group_bar(barid);
    }

    // ---- output Linear (final h in hbuf[0]; group-local) ----
    {
        const int bl = ltid / 10, k = ltid - (ltid / 10) * 10;  // 16 x 10
        const int b  = gid * 16 + bl;
        float sum = b_out[k];
        #pragma unroll
        for (int j = 0; j < LSTM_H; j++)
            sum = fmaf(hbuf[0][b * LSTM_H + j], w_out[k * LSTM_H + j], sum);
        out[(long)(b0 + b) * 10 + k] = sum;
    }
}

extern "C" void kernel_launch(void* const* d_in, const int* in_sizes, int n_in,
                              void* d_out, int out_size)
{
    const float* x     = (const float*)d_in[0];
    const float* w_ih  = (const float*)d_in[1];
    const float* w_hh  = (const float*)d_in[2];
    const float* b_ih  = (const float*)d_in[3];
    const float* b_hh  = (const float*)d_in[4];
    const float* w_out = (const float*)d_in[5];
    const float* b_out = (const float*)d_in[6];
    float* out = (float*)d_out;

    lstm_kernel<<<GRID, THREADS>>>(x, w_ih, w_hh, b_ih, b_hh, w_out, b_out, out);
}

// round 14
// speedup vs baseline: 1.4307x; 1.4307x over previous
#include <cuda_runtime.h>

// LSTM B=8192, T=512, I=12, H=20 (i,f,g,o), zero init; Linear(H->10) on h_T.
//
// R14 = R11 + 8-step full unroll (compile-time cur/nxt/buf/tt -> all SMEM
// accesses reg+imm, per-step ALU bookkeeping eliminated) + light phase
// stagger of the 4 barrier domains per SM.
//  - Thread = 2 gate rows x 1 unit x 4 batches, 32 u64 weights in regs;
//    partner (lane^1) holds the other 2 gates, combined via shfl.xor(1).
//  - Block 320 thr = 2 independent 160-thr groups (named barriers), BPB=32,
//    grid=256, __launch_bounds__(320,2).
//  - x staged per 4-step chunk via cp.async double-buffer (chunks 2m/2m+1
//    handled at s==0 / s==4 of each 8-step unrolled iteration).

#define LSTM_H   20
#define LSTM_I   12
#define LSTM_T   512
#define BPB      32
#define THREADS  320
#define GRID     256
#define XROW     52    // floats per batch row in xs (208B, 16B-aligned)

typedef unsigned long long u64;
typedef unsigned int       u32;

__device__ __forceinline__ u64 pack2(float lo, float hi) {
    u64 r; asm("mov.b64 %0, {%1, %2};" : "=l"(r) : "f"(lo), "f"(hi)); return r;
}
__device__ __forceinline__ void unpack2(u64 v, float& lo, float& hi) {
    asm("mov.b64 {%0, %1}, %2;" : "=f"(lo), "=f"(hi) : "l"(v));
}
__device__ __forceinline__ u64 fma2(u64 a, u64 b, u64 c) {
    u64 r; asm("fma.rn.f32x2 %0, %1, %2, %3;" : "=l"(r) : "l"(a), "l"(b), "l"(c));
    return r;
}
__device__ __forceinline__ float hadd2(u64 v) {
    float lo, hi; unpack2(v, lo, hi); return lo + hi;
}
__device__ __forceinline__ float tanhA(float x) {
    float y; asm("tanh.approx.f32 %0, %1;" : "=f"(y) : "f"(x)); return y;
}
__device__ __forceinline__ float sigA(float x) {
    return fmaf(tanhA(0.5f * x), 0.5f, 0.5f);
}
__device__ __forceinline__ void cp_async16(u32 smem_dst, const void* gsrc) {
    asm volatile("cp.async.ca.shared.global [%0], [%1], 16;\n"
                 :: "r"(smem_dst), "l"(gsrc) : "memory");
}
__device__ __forceinline__ void cp_commit() {
    asm volatile("cp.async.commit_group;\n" ::: "memory");
}
template<int N>
__device__ __forceinline__ void cp_wait() {
    asm volatile("cp.async.wait_group %0;\n" :: "n"(N) : "memory");
}
__device__ __forceinline__ void group_bar(int id) {
    asm volatile("bar.sync %0, %1;" :: "r"(id), "r"(160) : "memory");
}

// GEMV for one batch: 2 gate rows, bias folded into acc init.
__device__ __forceinline__ void gemv2(const u64* __restrict__ xr,
                                      const u64* __restrict__ hr,
                                      const u64* w0, const u64* w1,
                                      u64 binit0, u64 binit1,
                                      float& ga, float& gb)
{
    u64 a0 = binit0, a1 = binit1;
    #pragma unroll
    for (int k = 0; k < 6; k += 2) {
        ulonglong2 xv = *(const ulonglong2*)(xr + k);
        a0 = fma2(w0[k], xv.x, a0); a0 = fma2(w0[k+1], xv.y, a0);
        a1 = fma2(w1[k], xv.x, a1); a1 = fma2(w1[k+1], xv.y, a1);
    }
    #pragma unroll
    for (int k = 0; k < 10; k += 2) {
        ulonglong2 hv = *(const ulonglong2*)(hr + k);
        a0 = fma2(w0[6+k], hv.x, a0); a0 = fma2(w0[6+k+1], hv.y, a0);
        a1 = fma2(w1[6+k], hv.x, a1); a1 = fma2(w1[6+k+1], hv.y, a1);
    }
    ga = hadd2(a0);
    gb = hadd2(a1);
}

__global__ void __launch_bounds__(THREADS, 2)
lstm_kernel(const float* __restrict__ x,
            const float* __restrict__ w_ih,
            const float* __restrict__ w_hh,
            const float* __restrict__ b_ih,
            const float* __restrict__ b_hh,
            const float* __restrict__ w_out,
            const float* __restrict__ b_out,
            float* __restrict__ out)
{
    __shared__ __align__(16) float wcomb[80 * 32];           // 10240 B
    __shared__ __align__(16) float hbuf[2][BPB * LSTM_H];    //  5120 B
    __shared__ __align__(16) float xs[2][BPB * XROW];        // 13312 B

    const int tid  = threadIdx.x;
    const int gid  = tid / 160;          // group 0/1 (owns 16 batches)
    const int ltid = tid - gid * 160;
    const int quad = tid / 40;           // 0..7 (global)
    const int r    = tid % 40;
    const int u    = r >> 1;             // unit 0..19
    const int gh   = r & 1;              // 0 -> (i,g), 1 -> (f,o)
    const int b0   = blockIdx.x * BPB;
    const int q4   = quad * 4;
    const int barid = 1 + gid;

    const int row0 = gh ? (20 + u) : u;          // f : i
    const int row1 = gh ? (60 + u) : (40 + u);   // o : g

    // ---- stage combined weight rows into SMEM ----
    for (int i = tid; i < 80 * LSTM_I; i += THREADS) {
        int rr = i / LSTM_I, k = i - rr * LSTM_I;
        wcomb[rr * 32 + k] = w_ih[i];
    }
    for (int i = tid; i < 80 * LSTM_H; i += THREADS) {
        int rr = i / LSTM_H, k = i - rr * LSTM_H;
        wcomb[rr * 32 + 12 + k] = w_hh[i];
    }
    for (int i = tid; i < BPB * LSTM_H; i += THREADS) hbuf[0][i] = 0.f;

    const u64 binit0 = pack2(b_ih[row0] + b_hh[row0], 0.f);
    const u64 binit1 = pack2(b_ih[row1] + b_hh[row1], 0.f);

    // ---- cp.async: chunk0 -> xs[0], chunk1 -> xs[1] (group-local 16 batches) ----
    const float4* x4 = (const float4*)x;
    const u32 xs_base = (u32)__cvta_generic_to_shared(&xs[0][0]);
    {
        #pragma unroll 1
        for (int e = ltid; e < 16 * 12; e += 160) {
            int b = gid * 16 + e / 12, q = e - (e / 12) * 12;
            cp_async16(xs_base + (u32)((b * XROW + q * 4) * 4),
                       x4 + (long)(b0 + b) * 1536 + q);
        }
        cp_commit();
        #pragma unroll 1
        for (int e = ltid; e < 16 * 12; e += 160) {
            int b = gid * 16 + e / 12, q = e - (e / 12) * 12;
            cp_async16(xs_base + (u32)((BPB * XROW + b * XROW + q * 4) * 4),
                       x4 + (long)(b0 + b) * 1536 + 12 + q);
        }
        cp_commit();
    }
    cp_wait<1>();          // chunk 0 landed
    __syncthreads();       // wcomb + hbuf + chunk0 visible

    // ---- this thread's 2 gate rows into registers (32 u64 = 64 regs) ----
    u64 w0[16], w1[16];
    {
        const u64* p0 = (const u64*)&wcomb[row0 * 32];
        const u64* p1 = (const u64*)&wcomb[row1 * 32];
        #pragma unroll
        for (int k = 0; k < 16; k++) { w0[k] = p0[k]; w1[k] = p1[k]; }
    }

    // ---- light phase stagger of the 4 barrier domains per SM ----
    {
        const int phase = ((blockIdx.x & 1) << 1) | gid;   // 0..3
        for (int s = 0; s < phase * 2; s++) group_bar(barid);
    }

    float c0 = 0.f, c1 = 0.f;   // my 2 owned batches: q4+2*gh, q4+2*gh+1

    // ---- main loop: 64 iterations x 8 steps (2 chunks), fully unrolled body ----
    #pragma unroll 1
    for (int m = 0; m < 64; m++) {
        #pragma unroll
        for (int s = 0; s < 8; s++) {
            // staging points (s and buffers compile-time after unroll)
            if (s == 0) {
                if (m > 0) {
                    cp_wait<0>();
                    group_bar(barid);
                    // issue chunk 2m+1 -> buf1 (source steps 8m+4..8m+7)
                    const long tof = (long)(8 * m + 4) * 3;
                    #pragma unroll 1
                    for (int e = ltid; e < 16 * 12; e += 160) {
                        int b = gid * 16 + e / 12, q = e - (e / 12) * 12;
                        cp_async16(xs_base + (u32)((BPB * XROW + b * XROW + q * 4) * 4),
                                   x4 + (long)(b0 + b) * 1536 + tof + q);
                    }
                    cp_commit();
                }
            } else if (s == 4) {
                cp_wait<0>();
                group_bar(barid);
                if (m < 63) {
                    // issue chunk 2m+2 -> buf0 (source steps 8m+8..8m+11)
                    const long tof = (long)(8 * m + 8) * 3;
                    #pragma unroll 1
                    for (int e = ltid; e < 16 * 12; e += 160) {
                        int b = gid * 16 + e / 12, q = e - (e / 12) * 12;
                        cp_async16(xs_base + (u32)((b * XROW + q * 4) * 4),
                                   x4 + (long)(b0 + b) * 1536 + tof + q);
                    }
                    cp_commit();
                }
            }

            const int cur  = s & 1;          // compile-time after unroll
            const int nxt  = cur ^ 1;
            const int bufi = s >> 2;
            const int tt   = s & 3;

            const float* xb = &xs[bufi][tt * 12];
            const float* hb = &hbuf[cur][0];
            float* hn = &hbuf[nxt][0];

            float gA[4], gB[4];
            #pragma unroll
            for (int j = 0; j < 4; j++)
                gemv2((const u64*)(xb + (q4 + j) * XROW),
                      (const u64*)(hb + (q4 + j) * LSTM_H),
                      w0, w1, binit0, binit1, gA[j], gB[j]);

            // ---- exchange + epilogue, pairs p=0 (j 0/2) and p=1 (j 1/3) ----
            #pragma unroll
            for (int p = 0; p < 2; p++) {
                float sendA = gh ? gA[p]     : gA[2 + p];
                float sendB = gh ? gB[p]     : gB[2 + p];
                float ownA  = gh ? gA[2 + p] : gA[p];
                float ownB  = gh ? gB[2 + p] : gB[p];
                float recvA = __shfl_xor_sync(0xffffffffu, sendA, 1);
                float recvB = __shfl_xor_sync(0xffffffffu, sendB, 1);
                float gi = gh ? recvA : ownA;
                float gg = gh ? recvB : ownB;
                float gf = gh ? ownA  : recvA;
                float go = gh ? ownB  : recvB;
                float c  = p ? c1 : c0;
                c = sigA(gf) * c + sigA(gi) * tanhA(gg);
                if (p) c1 = c; else c0 = c;
                hn[(q4 + 2 * gh + p) * LSTM_H + u] = sigA(go) * tanhA(c);
            }
            group_bar(barid);
        }
    }

    // ---- output Linear (final h in hbuf[0]: t=511 -> nxt=0; group-local) ----
    {
        const int bl = ltid / 10, k = ltid - (ltid / 10) * 10;  // 16 x 10
        const int b  = gid * 16 + bl;
        float sum = b_out[k];
        #pragma unroll
        for (int j = 0; j < LSTM_H; j++)
            sum = fmaf(hbuf[0][b * LSTM_H + j], w_out[k * LSTM_H + j], sum);
        out[(long)(b0 + b) * 10 + k] = sum;
    }
}

extern "C" void kernel_launch(void* const* d_in, const int* in_sizes, int n_in,
                              void* d_out, int out_size)
{
    const float* x     = (const float*)d_in[0];
    const float* w_ih  = (const float*)d_in[1];
    const float* w_hh  = (const float*)d_in[2];
    const float* b_ih  = (const float*)d_in[3];
    const float* b_hh  = (const float*)d_in[4];
    const float* w_out = (const float*)d_in[5];
    const float* b_out = (const float*)d_in[6];
    float* out = (float*)d_out;

    lstm_kernel<<<GRID, THREADS>>>(x, w_ih, w_hh, b_ih, b_hh, w_out, b_out, out);
}